// round 11
// baseline (speedup 1.0000x reference)
#include <cuda_runtime.h>
#include <cuda_bf16.h>
#include <cstdint>

// Problem constants (match reference_code)
#define NN 50000
#define EE 800000
#define D_IN  128
#define D_H1  256
#define D_H2  128

// ---------------------------------------------------------------------------
// Static device scratch (allocation-free rule: __device__ globals)
// ---------------------------------------------------------------------------
__device__ float g_tmp[(size_t)NN * D_H1];   // pre-aggregation x@W (max N x 256)
__device__ float g_agg[(size_t)NN * D_H1];   // aggregation accumulator
__device__ float g_dis[NN];                  // rsqrt(deg)
__device__ int   g_deg[NN];
__device__ float g_norm[EE];                 // dis[src]*dis[dst]

// ---------------------------------------------------------------------------
// Helpers
// ---------------------------------------------------------------------------
__device__ __forceinline__ void red_add_v4(float4* addr, float x, float y, float z, float w) {
    asm volatile("red.global.add.v4.f32 [%0], {%1, %2, %3, %4};"
                 :: "l"(addr), "f"(x), "f"(y), "f"(z), "f"(w)
                 : "memory");
}

// ---------------------------------------------------------------------------
// Degree / normalization
// ---------------------------------------------------------------------------
__global__ void zero_int_kernel(int* p, int n) {
    int i = blockIdx.x * blockDim.x + threadIdx.x;
    if (i < n) p[i] = 0;
}

__global__ void zero_f4_kernel(float4* p, int n4) {
    int i = blockIdx.x * blockDim.x + threadIdx.x;
    if (i < n4) p[i] = make_float4(0.f, 0.f, 0.f, 0.f);
}

__global__ void count_deg_kernel(const int* __restrict__ dst, int e) {
    int i = blockIdx.x * blockDim.x + threadIdx.x;
    if (i < e) atomicAdd(&g_deg[dst[i]], 1);
}

__global__ void compute_dis_kernel(int n) {
    int i = blockIdx.x * blockDim.x + threadIdx.x;
    if (i < n) g_dis[i] = rsqrtf((float)(g_deg[i] + 1));  // +1 self loop, >=1
}

__global__ void compute_norm_kernel(const int* __restrict__ src,
                                    const int* __restrict__ dst, int e) {
    int i = blockIdx.x * blockDim.x + threadIdx.x;
    if (i < e) g_norm[i] = g_dis[src[i]] * g_dis[dst[i]];
}

// ---------------------------------------------------------------------------
// SGEMM: C[n x m] = A[n x k] @ B[k x m], row-major, fp32.
// 64x64 tile, BK=16, 256 threads, 4x4 per thread.
// k, m assumed multiples of 16 / 64 respectively (128/256 here).
// ---------------------------------------------------------------------------
__global__ __launch_bounds__(256)
void sgemm_kernel(const float* __restrict__ A, const float* __restrict__ B,
                  float* __restrict__ C, int n, int k, int m) {
    constexpr int BM = 64, BN = 64, BK = 16;
    __shared__ float As[BK][BM + 4];  // k-major A tile (padded)
    __shared__ float Bs[BK][BN];

    const int tid = threadIdx.x;
    const int tx = tid & 15;        // 0..15 (N dim)
    const int ty = tid >> 4;        // 0..15 (M dim)
    const int rowBase = blockIdx.y * BM;
    const int colBase = blockIdx.x * BN;

    float acc[4][4];
#pragma unroll
    for (int i = 0; i < 4; i++)
#pragma unroll
        for (int j = 0; j < 4; j++) acc[i][j] = 0.f;

    for (int k0 = 0; k0 < k; k0 += BK) {
        // Load A tile (64 rows x 16 k), transpose into As[k][row]
        {
            int l  = tid * 4;          // 0..1020
            int ar = l >> 4;           // row in tile 0..63
            int ak = l & 15;           // 0,4,8,12
            int grow = rowBase + ar;
            float4 v = make_float4(0.f, 0.f, 0.f, 0.f);
            if (grow < n)
                v = *(const float4*)(A + (size_t)grow * k + k0 + ak);
            As[ak + 0][ar] = v.x;
            As[ak + 1][ar] = v.y;
            As[ak + 2][ar] = v.z;
            As[ak + 3][ar] = v.w;
        }
        // Load B tile (16 k x 64 cols)
        {
            int l  = tid * 4;
            int br = l >> 6;           // 0..15
            int bc = l & 63;
            *(float4*)&Bs[br][bc] =
                *(const float4*)(B + (size_t)(k0 + br) * m + colBase + bc);
        }
        __syncthreads();

#pragma unroll
        for (int kk = 0; kk < BK; kk++) {
            float4 a4 = *(const float4*)&As[kk][ty * 4];
            float4 b4 = *(const float4*)&Bs[kk][tx * 4];
            float av[4] = {a4.x, a4.y, a4.z, a4.w};
            float bv[4] = {b4.x, b4.y, b4.z, b4.w};
#pragma unroll
            for (int i = 0; i < 4; i++)
#pragma unroll
                for (int j = 0; j < 4; j++)
                    acc[i][j] = fmaf(av[i], bv[j], acc[i][j]);
        }
        __syncthreads();
    }

#pragma unroll
    for (int i = 0; i < 4; i++) {
        int grow = rowBase + ty * 4 + i;
        if (grow < n) {
            float4 o = make_float4(acc[i][0], acc[i][1], acc[i][2], acc[i][3]);
            *(float4*)(C + (size_t)grow * m + colBase + tx * 4) = o;
        }
    }
}

// ---------------------------------------------------------------------------
// Edge aggregation: one warp per edge, D floats per row.
// agg[dst] += norm * tmp[src]   via red.global.add.v4.f32
// ---------------------------------------------------------------------------
template <int D>
__global__ __launch_bounds__(256)
void edge_agg_kernel(const int* __restrict__ src, const int* __restrict__ dst,
                     const float* __restrict__ tmp, float* __restrict__ agg, int e) {
    int gtid = blockIdx.x * blockDim.x + threadIdx.x;
    int edge = gtid >> 5;
    if (edge >= e) return;
    int lane = threadIdx.x & 31;

    int s = __ldg(&src[edge]);
    int d = __ldg(&dst[edge]);
    float w = __ldg(&g_norm[edge]);

    const float4* hp = (const float4*)(tmp + (size_t)s * D);
    float4* ap = (float4*)(agg + (size_t)d * D);

#pragma unroll
    for (int r = 0; r < D / 128; r++) {
        float4 v = __ldg(&hp[lane + r * 32]);
        red_add_v4(&ap[lane + r * 32], w * v.x, w * v.y, w * v.z, w * v.w);
    }
}

// Scalar edge aggregation for the 1-wide final layer.
__global__ void edge_agg1_kernel(const int* __restrict__ src,
                                 const int* __restrict__ dst,
                                 const float* __restrict__ tmp,
                                 float* __restrict__ agg, int e) {
    int i = blockIdx.x * blockDim.x + threadIdx.x;
    if (i >= e) return;
    atomicAdd(&agg[dst[i]], g_norm[i] * __ldg(&tmp[src[i]]));
}

// ---------------------------------------------------------------------------
// Epilogue: out = [relu](agg + dis^2 * tmp + b)   (self-loop folded in)
// ---------------------------------------------------------------------------
template <int D, bool RELU>
__global__ void epilogue_kernel(const float* __restrict__ agg,
                                const float* __restrict__ tmp,
                                const float* __restrict__ b,
                                float* __restrict__ out, int n) {
    int idx = blockIdx.x * blockDim.x + threadIdx.x;  // over n*D/4 float4s
    int total = n * (D / 4);
    if (idx >= total) return;
    int i  = idx / (D / 4);
    int jv = idx % (D / 4);
    float dis = g_dis[i];
    float d2 = dis * dis;
    float4 a = ((const float4*)agg)[idx];
    float4 t = ((const float4*)tmp)[idx];
    float4 bb = ((const float4*)b)[jv];
    float4 o;
    o.x = fmaf(d2, t.x, a.x) + bb.x;
    o.y = fmaf(d2, t.y, a.y) + bb.y;
    o.z = fmaf(d2, t.z, a.z) + bb.z;
    o.w = fmaf(d2, t.w, a.w) + bb.w;
    if (RELU) {
        o.x = fmaxf(o.x, 0.f);
        o.y = fmaxf(o.y, 0.f);
        o.z = fmaxf(o.z, 0.f);
        o.w = fmaxf(o.w, 0.f);
    }
    ((float4*)out)[idx] = o;
}

__global__ void epilogue_y_kernel(const float* __restrict__ agg,
                                  const float* __restrict__ tmp,
                                  const float* __restrict__ b3,
                                  float* __restrict__ y, int n) {
    int i = blockIdx.x * blockDim.x + threadIdx.x;
    if (i >= n) return;
    float dis = g_dis[i];
    y[i] = fmaf(dis * dis, tmp[i], agg[i]) + b3[0];
}

// ---------------------------------------------------------------------------
// Final 128->1 projection: one warp per node, warp-shuffle reduce.
// ---------------------------------------------------------------------------
__global__ __launch_bounds__(256)
void dot_w3_kernel(const float* __restrict__ h2, const float* __restrict__ w3,
                   float* __restrict__ out, int n) {
    int gtid = blockIdx.x * blockDim.x + threadIdx.x;
    int row = gtid >> 5;
    if (row >= n) return;
    int lane = threadIdx.x & 31;
    float4 h = __ldg((const float4*)(h2 + (size_t)row * 128) + lane);
    float4 w = __ldg((const float4*)w3 + lane);
    float s = h.x * w.x + h.y * w.y + h.z * w.z + h.w * w.w;
#pragma unroll
    for (int o = 16; o; o >>= 1) s += __shfl_xor_sync(0xFFFFFFFFu, s, o);
    if (lane == 0) out[row] = s;
}

// ---------------------------------------------------------------------------
// Launch
// ---------------------------------------------------------------------------
extern "C" void kernel_launch(void* const* d_in, const int* in_sizes, int n_in,
                              void* d_out, int out_size) {
    const float* x   = (const float*)d_in[0];
    const int*   ei  = (const int*)d_in[1];
    const float* W1  = (const float*)d_in[2];
    const float* b1  = (const float*)d_in[3];
    const float* W2  = (const float*)d_in[4];
    const float* b2  = (const float*)d_in[5];
    const float* W3  = (const float*)d_in[6];
    const float* b3  = (const float*)d_in[7];

    const int n = NN;
    const int e = EE;
    const int* src = ei;
    const int* dst = ei + e;

    float* out_y  = (float*)d_out;                         // [n]
    float* out_h1 = out_y + n;                             // [n*256]
    float* out_h2 = out_h1 + (size_t)n * D_H1;             // [n*128]

    float* tmp;  cudaGetSymbolAddress((void**)&tmp, g_tmp);
    float* agg;  cudaGetSymbolAddress((void**)&agg, g_agg);
    int*   deg;  cudaGetSymbolAddress((void**)&deg, g_deg);

    const int TB = 256;

    // --- degree + normalization ---
    zero_int_kernel<<<(n + TB - 1) / TB, TB>>>(deg, n);
    count_deg_kernel<<<(e + TB - 1) / TB, TB>>>(dst, e);
    compute_dis_kernel<<<(n + TB - 1) / TB, TB>>>(n);
    compute_norm_kernel<<<(e + TB - 1) / TB, TB>>>(src, dst, e);

    dim3 gemm_blk(256);

    // ================= Layer 1: 128 -> 256 =================
    {
        dim3 grid(D_H1 / 64, (n + 63) / 64);
        sgemm_kernel<<<grid, gemm_blk>>>(x, W1, tmp, n, D_IN, D_H1);

        int n4 = n * (D_H1 / 4);
        zero_f4_kernel<<<(n4 + TB - 1) / TB, TB>>>((float4*)agg, n4);

        long long thr = (long long)e * 32;
        edge_agg_kernel<D_H1><<<(unsigned)((thr + TB - 1) / TB), TB>>>(src, dst, tmp, agg, e);

        epilogue_kernel<D_H1, true><<<(n4 + TB - 1) / TB, TB>>>(agg, tmp, b1, out_h1, n);
    }

    // ================= Layer 2: 256 -> 128 =================
    {
        dim3 grid(D_H2 / 64, (n + 63) / 64);
        sgemm_kernel<<<grid, gemm_blk>>>(out_h1, W2, tmp, n, D_H1, D_H2);

        int n4 = n * (D_H2 / 4);
        zero_f4_kernel<<<(n4 + TB - 1) / TB, TB>>>((float4*)agg, n4);

        long long thr = (long long)e * 32;
        edge_agg_kernel<D_H2><<<(unsigned)((thr + TB - 1) / TB), TB>>>(src, dst, tmp, agg, e);

        epilogue_kernel<D_H2, true><<<(n4 + TB - 1) / TB, TB>>>(agg, tmp, b2, out_h2, n);
    }

    // ================= Layer 3: 128 -> 1 =================
    {
        long long thr = (long long)n * 32;
        dot_w3_kernel<<<(unsigned)((thr + TB - 1) / TB), TB>>>(out_h2, W3, tmp, n);

        int n4 = (n + 3) / 4;
        zero_f4_kernel<<<(n4 + TB - 1) / TB, TB>>>((float4*)agg, n4);

        edge_agg1_kernel<<<(e + TB - 1) / TB, TB>>>(src, dst, tmp, agg, e);

        epilogue_y_kernel<<<(n + TB - 1) / TB, TB>>>(agg, tmp, b3, out_y, n);
    }
}

// round 12
// speedup vs baseline: 1.3000x; 1.3000x over previous
#include <cuda_runtime.h>
#include <cuda_bf16.h>
#include <cstdint>

// Problem constants (match reference_code)
#define NN 50000
#define EE 800000
#define D_IN  128
#define D_H1  256
#define D_H2  128

// ---------------------------------------------------------------------------
// Static device scratch (allocation-free rule: __device__ globals)
// ---------------------------------------------------------------------------
__device__ float g_buf[(size_t)NN * 128];    // xhat (L1) / tmp (L2), reused
__device__ float g_z[NN];                    // h2 @ W3 (pre-aggregation)
__device__ float g_dis[NN];                  // rsqrt(deg+1)
__device__ int   g_deg[NN];
__device__ int   g_rowstart[NN + 1];         // CSR row offsets (by dst)
__device__ int   g_cursor[NN];               // scatter cursors
__device__ int   g_ssrc[EE];                 // dst-sorted src indices
__device__ float g_snorm[EE];                // dst-sorted edge norms

// ---------------------------------------------------------------------------
// Degree / normalization / CSR build
// ---------------------------------------------------------------------------
__global__ void zero_int_kernel(int* p, int n) {
    int i = blockIdx.x * blockDim.x + threadIdx.x;
    if (i < n) p[i] = 0;
}

__global__ void count_deg_kernel(const int* __restrict__ dst, int e) {
    int i = blockIdx.x * blockDim.x + threadIdx.x;
    if (i < e) atomicAdd(&g_deg[dst[i]], 1);
}

__global__ void compute_dis_kernel(int n) {
    int i = blockIdx.x * blockDim.x + threadIdx.x;
    if (i < n) g_dis[i] = rsqrtf((float)(g_deg[i] + 1));  // +1 self loop
}

// Single-block exclusive scan of g_deg -> g_rowstart / g_cursor. 1024 threads.
__global__ void scan_kernel(int n) {
    __shared__ int warp_sums[32];
    __shared__ int chunk_total_sh;
    const int tid = threadIdx.x;
    const int lane = tid & 31;
    const int wid = tid >> 5;
    int offset = 0;

    for (int base = 0; base < n; base += 1024) {
        int idx = base + tid;
        int v = (idx < n) ? g_deg[idx] : 0;

        // warp inclusive scan
        int incl = v;
#pragma unroll
        for (int o = 1; o < 32; o <<= 1) {
            int t = __shfl_up_sync(0xffffffffu, incl, o);
            if (lane >= o) incl += t;
        }
        if (lane == 31) warp_sums[wid] = incl;
        __syncthreads();

        if (wid == 0) {
            int t = warp_sums[lane];
            int s = t;
#pragma unroll
            for (int o = 1; o < 32; o <<= 1) {
                int u = __shfl_up_sync(0xffffffffu, s, o);
                if (lane >= o) s += u;
            }
            warp_sums[lane] = s - t;  // exclusive warp offsets
            if (lane == 31) chunk_total_sh = s;
        }
        __syncthreads();

        int excl = offset + warp_sums[wid] + (incl - v);
        if (idx < n) {
            g_rowstart[idx] = excl;
            g_cursor[idx] = excl;
        }
        offset += chunk_total_sh;
        __syncthreads();  // protect shared before next chunk overwrites
    }
    if (tid == 0) g_rowstart[n] = offset;
}

__global__ void scatter_kernel(const int* __restrict__ src,
                               const int* __restrict__ dst, int e) {
    int i = blockIdx.x * blockDim.x + threadIdx.x;
    if (i >= e) return;
    int s = src[i];
    int d = dst[i];
    int pos = atomicAdd(&g_cursor[d], 1);
    g_ssrc[pos] = s;
    g_snorm[pos] = g_dis[s] * g_dis[d];
}

// ---------------------------------------------------------------------------
// CSR aggregation, D=128, one warp per dst node.
// out[row] = dis[row]^2 * in[row] + sum_e norm_e * in[src_e]
// EPI: out = relu(out + bias); DOT: z[row] = out . w3
// ---------------------------------------------------------------------------
template <bool EPI, bool DOT>
__global__ __launch_bounds__(256)
void csr_agg128_kernel(const float* __restrict__ in, float* __restrict__ out,
                       const float* __restrict__ bias,
                       const float* __restrict__ w3,
                       float* __restrict__ z, int n) {
    int gw = (blockIdx.x * blockDim.x + threadIdx.x) >> 5;
    if (gw >= n) return;
    int lane = threadIdx.x & 31;

    int beg = __ldg(&g_rowstart[gw]);
    int end = __ldg(&g_rowstart[gw + 1]);
    float dis = g_dis[gw];
    float d2 = dis * dis;

    float4 sv = __ldg((const float4*)(in + (size_t)gw * 128) + lane);
    float4 acc = make_float4(d2 * sv.x, d2 * sv.y, d2 * sv.z, d2 * sv.w);

    for (int p = beg; p < end; p += 32) {
        int cnt = min(32, end - p);
        int sidx = 0;
        float w = 0.f;
        if (lane < cnt) {
            sidx = __ldg(&g_ssrc[p + lane]);
            w = __ldg(&g_snorm[p + lane]);
        }
#pragma unroll 4
        for (int j = 0; j < cnt; j++) {
            int s = __shfl_sync(0xffffffffu, sidx, j);
            float ww = __shfl_sync(0xffffffffu, w, j);
            float4 v = __ldg((const float4*)(in + (size_t)s * 128) + lane);
            acc.x = fmaf(ww, v.x, acc.x);
            acc.y = fmaf(ww, v.y, acc.y);
            acc.z = fmaf(ww, v.z, acc.z);
            acc.w = fmaf(ww, v.w, acc.w);
        }
    }

    if (EPI) {
        float4 bb = __ldg((const float4*)bias + lane);
        acc.x = fmaxf(acc.x + bb.x, 0.f);
        acc.y = fmaxf(acc.y + bb.y, 0.f);
        acc.z = fmaxf(acc.z + bb.z, 0.f);
        acc.w = fmaxf(acc.w + bb.w, 0.f);
    }
    ((float4*)(out + (size_t)gw * 128))[lane] = acc;

    if (DOT) {
        float4 wv = __ldg((const float4*)w3 + lane);
        float s = acc.x * wv.x + acc.y * wv.y + acc.z * wv.z + acc.w * wv.w;
#pragma unroll
        for (int o = 16; o; o >>= 1) s += __shfl_xor_sync(0xffffffffu, s, o);
        if (lane == 0) z[gw] = s;
    }
}

// Scalar CSR aggregation for the 1-wide final layer. One warp per dst node.
__global__ __launch_bounds__(256)
void csr_agg1_kernel(const float* __restrict__ zin,
                     const float* __restrict__ b3,
                     float* __restrict__ y, int n) {
    int gw = (blockIdx.x * blockDim.x + threadIdx.x) >> 5;
    if (gw >= n) return;
    int lane = threadIdx.x & 31;
    int beg = __ldg(&g_rowstart[gw]);
    int end = __ldg(&g_rowstart[gw + 1]);
    float acc = 0.f;
    for (int p = beg + lane; p < end; p += 32)
        acc = fmaf(__ldg(&g_snorm[p]), __ldg(&zin[__ldg(&g_ssrc[p])]), acc);
#pragma unroll
    for (int o = 16; o; o >>= 1) acc += __shfl_xor_sync(0xffffffffu, acc, o);
    if (lane == 0) {
        float dis = g_dis[gw];
        y[gw] = acc + dis * dis * zin[gw] + b3[0];
    }
}

// ---------------------------------------------------------------------------
// SGEMM: C[n x m] = A[n x k] @ B[k x m], fp32, row-major.
// 128x128 tile, BK=8, 256 threads, 8x8 per thread, smem double-buffered.
// k multiple of 8, m multiple of 128. Optional fused bias + relu.
// ---------------------------------------------------------------------------
template <bool BIAS_RELU>
__global__ __launch_bounds__(256)
void sgemm128_kernel(const float* __restrict__ A, const float* __restrict__ B,
                     const float* __restrict__ bias, float* __restrict__ C,
                     int n, int k, int m) {
    constexpr int BM = 128, BN = 128, BK = 8;
    __shared__ float As[2][BK][BM];
    __shared__ float Bs[2][BK][BN];

    const int tid = threadIdx.x;
    const int rowBase = blockIdx.y * BM;
    const int colBase = blockIdx.x * BN;

    // A loader: 128 rows x 8 k = 256 float4 -> one per thread
    const int ar = tid >> 1;          // 0..127
    const int ak = (tid & 1) * 4;     // 0 or 4
    // B loader: 8 rows x 128 cols = 256 float4
    const int br = tid >> 5;          // 0..7
    const int bc = (tid & 31) * 4;    // 0..124

    const int tx = tid & 15;          // col group
    const int ty = tid >> 4;          // row group

    float acc[8][8];
#pragma unroll
    for (int i = 0; i < 8; i++)
#pragma unroll
        for (int j = 0; j < 8; j++) acc[i][j] = 0.f;

    const int nk = k / BK;
    const int grow = rowBase + ar;

    // prologue: tile 0
    float4 pA = make_float4(0.f, 0.f, 0.f, 0.f);
    if (grow < n) pA = *(const float4*)(A + (size_t)grow * k + ak);
    float4 pB = *(const float4*)(B + (size_t)br * m + colBase + bc);
    As[0][ak + 0][ar] = pA.x;
    As[0][ak + 1][ar] = pA.y;
    As[0][ak + 2][ar] = pA.z;
    As[0][ak + 3][ar] = pA.w;
    *(float4*)&Bs[0][br][bc] = pB;
    __syncthreads();

    for (int kt = 0; kt < nk; kt++) {
        const int cur = kt & 1;
        if (kt + 1 < nk) {
            int k0 = (kt + 1) * BK;
            pA = make_float4(0.f, 0.f, 0.f, 0.f);
            if (grow < n) pA = *(const float4*)(A + (size_t)grow * k + k0 + ak);
            pB = *(const float4*)(B + (size_t)(k0 + br) * m + colBase + bc);
        }

#pragma unroll
        for (int kk = 0; kk < BK; kk++) {
            float a[8], b[8];
            *(float4*)&a[0] = *(const float4*)&As[cur][kk][ty * 8];
            *(float4*)&a[4] = *(const float4*)&As[cur][kk][ty * 8 + 4];
            *(float4*)&b[0] = *(const float4*)&Bs[cur][kk][tx * 8];
            *(float4*)&b[4] = *(const float4*)&Bs[cur][kk][tx * 8 + 4];
#pragma unroll
            for (int i = 0; i < 8; i++)
#pragma unroll
                for (int j = 0; j < 8; j++)
                    acc[i][j] = fmaf(a[i], b[j], acc[i][j]);
        }

        if (kt + 1 < nk) {
            const int nxt = cur ^ 1;
            As[nxt][ak + 0][ar] = pA.x;
            As[nxt][ak + 1][ar] = pA.y;
            As[nxt][ak + 2][ar] = pA.z;
            As[nxt][ak + 3][ar] = pA.w;
            *(float4*)&Bs[nxt][br][bc] = pB;
            __syncthreads();
        }
    }

    // epilogue
    float4 bias0 = make_float4(0.f, 0.f, 0.f, 0.f);
    float4 bias1 = make_float4(0.f, 0.f, 0.f, 0.f);
    if (BIAS_RELU) {
        bias0 = *(const float4*)(bias + colBase + tx * 8);
        bias1 = *(const float4*)(bias + colBase + tx * 8 + 4);
    }
#pragma unroll
    for (int i = 0; i < 8; i++) {
        int r = rowBase + ty * 8 + i;
        if (r >= n) break;
        float4 o0 = make_float4(acc[i][0], acc[i][1], acc[i][2], acc[i][3]);
        float4 o1 = make_float4(acc[i][4], acc[i][5], acc[i][6], acc[i][7]);
        if (BIAS_RELU) {
            o0.x = fmaxf(o0.x + bias0.x, 0.f);
            o0.y = fmaxf(o0.y + bias0.y, 0.f);
            o0.z = fmaxf(o0.z + bias0.z, 0.f);
            o0.w = fmaxf(o0.w + bias0.w, 0.f);
            o1.x = fmaxf(o1.x + bias1.x, 0.f);
            o1.y = fmaxf(o1.y + bias1.y, 0.f);
            o1.z = fmaxf(o1.z + bias1.z, 0.f);
            o1.w = fmaxf(o1.w + bias1.w, 0.f);
        }
        *(float4*)(C + (size_t)r * m + colBase + tx * 8) = o0;
        *(float4*)(C + (size_t)r * m + colBase + tx * 8 + 4) = o1;
    }
}

// ---------------------------------------------------------------------------
// Launch
// ---------------------------------------------------------------------------
extern "C" void kernel_launch(void* const* d_in, const int* in_sizes, int n_in,
                              void* d_out, int out_size) {
    const float* x  = (const float*)d_in[0];
    const int*   ei = (const int*)d_in[1];
    const float* W1 = (const float*)d_in[2];
    const float* b1 = (const float*)d_in[3];
    const float* W2 = (const float*)d_in[4];
    const float* b2 = (const float*)d_in[5];
    const float* W3 = (const float*)d_in[6];
    const float* b3 = (const float*)d_in[7];

    const int n = NN;
    const int e = EE;
    const int* src = ei;
    const int* dst = ei + e;

    float* out_y  = (float*)d_out;                 // [n]
    float* out_h1 = out_y + n;                     // [n*256]
    float* out_h2 = out_h1 + (size_t)n * D_H1;     // [n*128]

    float* buf;  cudaGetSymbolAddress((void**)&buf, g_buf);
    float* z;    cudaGetSymbolAddress((void**)&z, g_z);
    int*   deg;  cudaGetSymbolAddress((void**)&deg, g_deg);

    const int TB = 256;

    // --- CSR build: degree -> dis -> scan -> scatter (dst-sorted edges) ---
    zero_int_kernel<<<(n + TB - 1) / TB, TB>>>(deg, n);
    count_deg_kernel<<<(e + TB - 1) / TB, TB>>>(dst, e);
    compute_dis_kernel<<<(n + TB - 1) / TB, TB>>>(n);
    scan_kernel<<<1, 1024>>>(n);
    scatter_kernel<<<(e + TB - 1) / TB, TB>>>(src, dst, e);

    const int aggBlocks = (n * 32 + TB - 1) / TB;

    // ===== Layer 1: xhat = A_hat @ x  (128-wide), then h1 = relu(xhat@W1+b1)
    csr_agg128_kernel<false, false><<<aggBlocks, TB>>>(x, buf, nullptr, nullptr,
                                                       nullptr, n);
    {
        dim3 grid(D_H1 / 128, (n + 127) / 128);
        sgemm128_kernel<true><<<grid, TB>>>(buf, W1, b1, out_h1, n, D_IN, D_H1);
    }

    // ===== Layer 2: tmp = h1@W2, then h2 = relu(A_hat@tmp + b2), z = h2@W3
    {
        dim3 grid(D_H2 / 128, (n + 127) / 128);
        sgemm128_kernel<false><<<grid, TB>>>(out_h1, W2, nullptr, buf, n, D_H1,
                                             D_H2);
    }
    csr_agg128_kernel<true, true><<<aggBlocks, TB>>>(buf, out_h2, b2, W3, z, n);

    // ===== Layer 3: y = A_hat @ z + b3
    csr_agg1_kernel<<<aggBlocks, TB>>>(z, b3, out_y, n);
}

// round 13
// speedup vs baseline: 1.3168x; 1.0129x over previous
#include <cuda_runtime.h>
#include <cuda_bf16.h>
#include <cstdint>

// Problem constants (match reference_code)
#define NN 50000
#define EE 800000
#define D_IN  128
#define D_H1  256
#define D_H2  128

// ---------------------------------------------------------------------------
// Static device scratch (allocation-free rule: __device__ globals)
// ---------------------------------------------------------------------------
__device__ float g_buf[(size_t)NN * 128];    // xhat (L1) / tmp (L2), reused
__device__ float g_z[NN];                    // h2 @ W3 (pre-aggregation)
__device__ float g_dis[NN];                  // rsqrt(deg+1)
__device__ int   g_deg[NN];
__device__ int   g_rowstart[NN];             // CSR range begin (by dst)
__device__ int   g_cursor[NN];               // scatter cursors
__device__ int   g_total;                    // range allocator
__device__ int   g_ssrc[EE];                 // dst-sorted src indices
__device__ float g_snorm[EE];                // dst-sorted edge norms

// ---------------------------------------------------------------------------
// CSR build
// ---------------------------------------------------------------------------
__global__ void zero_deg_kernel(int n) {
    int i = blockIdx.x * blockDim.x + threadIdx.x;
    if (i < n) g_deg[i] = 0;
    if (i == 0) g_total = 0;
}

__global__ void count_deg_kernel(const int* __restrict__ dst, int e) {
    int i = blockIdx.x * blockDim.x + threadIdx.x;
    if (i < e) atomicAdd(&g_deg[dst[i]], 1);
}

// Per-block exclusive scan + atomic range reservation. Range order across
// blocks is arbitrary — only per-node contiguity matters. Also computes dis.
__global__ __launch_bounds__(256)
void alloc_ranges_kernel(int n) {
    __shared__ int warp_sums[8];
    __shared__ int base_sh;
    const int tid = threadIdx.x;
    const int lane = tid & 31;
    const int wid = tid >> 5;
    const int idx = blockIdx.x * 256 + tid;

    int v = (idx < n) ? g_deg[idx] : 0;
    if (idx < n) g_dis[idx] = rsqrtf((float)(v + 1));  // +1 self loop

    // warp inclusive scan
    int incl = v;
#pragma unroll
    for (int o = 1; o < 32; o <<= 1) {
        int t = __shfl_up_sync(0xffffffffu, incl, o);
        if (lane >= o) incl += t;
    }
    if (lane == 31) warp_sums[wid] = incl;
    __syncthreads();

    if (wid == 0) {
        int t = (lane < 8) ? warp_sums[lane] : 0;
        int s = t;
#pragma unroll
        for (int o = 1; o < 8; o <<= 1) {
            int u = __shfl_up_sync(0xffffffffu, s, o);
            if (lane >= o) s += u;
        }
        if (lane < 8) warp_sums[lane] = s - t;  // exclusive warp offsets
        if (lane == 7) base_sh = atomicAdd(&g_total, s);  // block total
    }
    __syncthreads();

    if (idx < n) {
        int excl = base_sh + warp_sums[wid] + (incl - v);
        g_rowstart[idx] = excl;
        g_cursor[idx] = excl;
    }
}

__global__ void scatter_kernel(const int* __restrict__ src,
                               const int* __restrict__ dst, int e) {
    int i = blockIdx.x * blockDim.x + threadIdx.x;
    if (i >= e) return;
    int s = src[i];
    int d = dst[i];
    int pos = atomicAdd(&g_cursor[d], 1);
    g_ssrc[pos] = s;
    g_snorm[pos] = g_dis[s] * g_dis[d];
}

// ---------------------------------------------------------------------------
// CSR aggregation, D=128, one warp per dst node.
// out[row] = dis[row]^2 * in[row] + sum_e norm_e * in[src_e]
// EPI: out = relu(out + bias); DOT: z[row] = out . w3
// ---------------------------------------------------------------------------
template <bool EPI, bool DOT>
__global__ __launch_bounds__(256)
void csr_agg128_kernel(const float* __restrict__ in, float* __restrict__ out,
                       const float* __restrict__ bias,
                       const float* __restrict__ w3,
                       float* __restrict__ z, int n) {
    int gw = (blockIdx.x * blockDim.x + threadIdx.x) >> 5;
    if (gw >= n) return;
    int lane = threadIdx.x & 31;

    int beg = __ldg(&g_rowstart[gw]);
    int end = beg + __ldg(&g_deg[gw]);
    float dis = g_dis[gw];
    float d2 = dis * dis;

    float4 sv = __ldg((const float4*)(in + (size_t)gw * 128) + lane);
    float4 acc = make_float4(d2 * sv.x, d2 * sv.y, d2 * sv.z, d2 * sv.w);

    for (int p = beg; p < end; p += 32) {
        int cnt = min(32, end - p);
        int sidx = 0;
        float w = 0.f;
        if (lane < cnt) {
            sidx = __ldg(&g_ssrc[p + lane]);
            w = __ldg(&g_snorm[p + lane]);
        }
#pragma unroll 4
        for (int j = 0; j < cnt; j++) {
            int s = __shfl_sync(0xffffffffu, sidx, j);
            float ww = __shfl_sync(0xffffffffu, w, j);
            float4 v = __ldg((const float4*)(in + (size_t)s * 128) + lane);
            acc.x = fmaf(ww, v.x, acc.x);
            acc.y = fmaf(ww, v.y, acc.y);
            acc.z = fmaf(ww, v.z, acc.z);
            acc.w = fmaf(ww, v.w, acc.w);
        }
    }

    if (EPI) {
        float4 bb = __ldg((const float4*)bias + lane);
        acc.x = fmaxf(acc.x + bb.x, 0.f);
        acc.y = fmaxf(acc.y + bb.y, 0.f);
        acc.z = fmaxf(acc.z + bb.z, 0.f);
        acc.w = fmaxf(acc.w + bb.w, 0.f);
    }
    ((float4*)(out + (size_t)gw * 128))[lane] = acc;

    if (DOT) {
        float4 wv = __ldg((const float4*)w3 + lane);
        float s = acc.x * wv.x + acc.y * wv.y + acc.z * wv.z + acc.w * wv.w;
#pragma unroll
        for (int o = 16; o; o >>= 1) s += __shfl_xor_sync(0xffffffffu, s, o);
        if (lane == 0) z[gw] = s;
    }
}

// Scalar CSR aggregation for the 1-wide final layer. One warp per dst node.
__global__ __launch_bounds__(256)
void csr_agg1_kernel(const float* __restrict__ zin,
                     const float* __restrict__ b3,
                     float* __restrict__ y, int n) {
    int gw = (blockIdx.x * blockDim.x + threadIdx.x) >> 5;
    if (gw >= n) return;
    int lane = threadIdx.x & 31;
    int beg = __ldg(&g_rowstart[gw]);
    int end = beg + __ldg(&g_deg[gw]);
    float acc = 0.f;
    for (int p = beg + lane; p < end; p += 32)
        acc = fmaf(__ldg(&g_snorm[p]), __ldg(&zin[__ldg(&g_ssrc[p])]), acc);
#pragma unroll
    for (int o = 16; o; o >>= 1) acc += __shfl_xor_sync(0xffffffffu, acc, o);
    if (lane == 0) {
        float dis = g_dis[gw];
        y[gw] = acc + dis * dis * zin[gw] + b3[0];
    }
}

// ---------------------------------------------------------------------------
// SGEMM: C[n x m] = A[n x k] @ B[k x m], fp32, row-major.
// BM x 128 tile, BK=8, 256 threads, (BM/16) x 8 per thread, double-buffered.
// k multiple of 8, m multiple of 128. Optional fused bias + relu.
// ---------------------------------------------------------------------------
template <int BM, bool BIAS_RELU>
__global__ __launch_bounds__(256)
void sgemm_kernel(const float* __restrict__ A, const float* __restrict__ B,
                  const float* __restrict__ bias, float* __restrict__ C,
                  int n, int k, int m) {
    constexpr int BN = 128, BK = 8;
    constexpr int R = BM / 16;            // rows per thread (4 or 8)
    constexpr int AVEC = BM * BK / 4;     // float4s in A tile (128 or 256)
    __shared__ float As[2][BK][BM];
    __shared__ float Bs[2][BK][BN];

    const int tid = threadIdx.x;
    const int rowBase = blockIdx.y * BM;
    const int colBase = blockIdx.x * BN;

    // A loader: BM rows x 8 k = AVEC float4 over first AVEC threads
    const int ar = tid >> 1;              // row in tile
    const int ak = (tid & 1) * 4;         // 0 or 4
    const bool aload = (tid < AVEC);
    // B loader: 8 rows x 128 cols = 256 float4
    const int br = tid >> 5;              // 0..7
    const int bc = (tid & 31) * 4;        // 0..124

    const int tx = tid & 15;              // col group (8 cols each)
    const int ty = tid >> 4;              // row group (R rows each)

    float acc[R][8];
#pragma unroll
    for (int i = 0; i < R; i++)
#pragma unroll
        for (int j = 0; j < 8; j++) acc[i][j] = 0.f;

    const int nk = k / BK;
    const int grow = rowBase + ar;

    // prologue: tile 0
    float4 pA = make_float4(0.f, 0.f, 0.f, 0.f);
    if (aload && grow < n) pA = *(const float4*)(A + (size_t)grow * k + ak);
    float4 pB = *(const float4*)(B + (size_t)br * m + colBase + bc);
    if (aload) {
        As[0][ak + 0][ar] = pA.x;
        As[0][ak + 1][ar] = pA.y;
        As[0][ak + 2][ar] = pA.z;
        As[0][ak + 3][ar] = pA.w;
    }
    *(float4*)&Bs[0][br][bc] = pB;
    __syncthreads();

    for (int kt = 0; kt < nk; kt++) {
        const int cur = kt & 1;
        if (kt + 1 < nk) {
            int k0 = (kt + 1) * BK;
            pA = make_float4(0.f, 0.f, 0.f, 0.f);
            if (aload && grow < n)
                pA = *(const float4*)(A + (size_t)grow * k + k0 + ak);
            pB = *(const float4*)(B + (size_t)(k0 + br) * m + colBase + bc);
        }

#pragma unroll
        for (int kk = 0; kk < BK; kk++) {
            float a[R], b[8];
#pragma unroll
            for (int i = 0; i < R; i += 4)
                *(float4*)&a[i] = *(const float4*)&As[cur][kk][ty * R + i];
            *(float4*)&b[0] = *(const float4*)&Bs[cur][kk][tx * 8];
            *(float4*)&b[4] = *(const float4*)&Bs[cur][kk][tx * 8 + 4];
#pragma unroll
            for (int i = 0; i < R; i++)
#pragma unroll
                for (int j = 0; j < 8; j++)
                    acc[i][j] = fmaf(a[i], b[j], acc[i][j]);
        }

        if (kt + 1 < nk) {
            const int nxt = cur ^ 1;
            if (aload) {
                As[nxt][ak + 0][ar] = pA.x;
                As[nxt][ak + 1][ar] = pA.y;
                As[nxt][ak + 2][ar] = pA.z;
                As[nxt][ak + 3][ar] = pA.w;
            }
            *(float4*)&Bs[nxt][br][bc] = pB;
            __syncthreads();
        }
    }

    // epilogue
    float4 bias0 = make_float4(0.f, 0.f, 0.f, 0.f);
    float4 bias1 = make_float4(0.f, 0.f, 0.f, 0.f);
    if (BIAS_RELU) {
        bias0 = *(const float4*)(bias + colBase + tx * 8);
        bias1 = *(const float4*)(bias + colBase + tx * 8 + 4);
    }
#pragma unroll
    for (int i = 0; i < R; i++) {
        int r = rowBase + ty * R + i;
        if (r >= n) break;
        float4 o0 = make_float4(acc[i][0], acc[i][1], acc[i][2], acc[i][3]);
        float4 o1 = make_float4(acc[i][4], acc[i][5], acc[i][6], acc[i][7]);
        if (BIAS_RELU) {
            o0.x = fmaxf(o0.x + bias0.x, 0.f);
            o0.y = fmaxf(o0.y + bias0.y, 0.f);
            o0.z = fmaxf(o0.z + bias0.z, 0.f);
            o0.w = fmaxf(o0.w + bias0.w, 0.f);
            o1.x = fmaxf(o1.x + bias1.x, 0.f);
            o1.y = fmaxf(o1.y + bias1.y, 0.f);
            o1.z = fmaxf(o1.z + bias1.z, 0.f);
            o1.w = fmaxf(o1.w + bias1.w, 0.f);
        }
        *(float4*)(C + (size_t)r * m + colBase + tx * 8) = o0;
        *(float4*)(C + (size_t)r * m + colBase + tx * 8 + 4) = o1;
    }
}

// ---------------------------------------------------------------------------
// Launch
// ---------------------------------------------------------------------------
extern "C" void kernel_launch(void* const* d_in, const int* in_sizes, int n_in,
                              void* d_out, int out_size) {
    const float* x  = (const float*)d_in[0];
    const int*   ei = (const int*)d_in[1];
    const float* W1 = (const float*)d_in[2];
    const float* b1 = (const float*)d_in[3];
    const float* W2 = (const float*)d_in[4];
    const float* b2 = (const float*)d_in[5];
    const float* W3 = (const float*)d_in[6];
    const float* b3 = (const float*)d_in[7];

    const int n = NN;
    const int e = EE;
    const int* src = ei;
    const int* dst = ei + e;

    float* out_y  = (float*)d_out;                 // [n]
    float* out_h1 = out_y + n;                     // [n*256]
    float* out_h2 = out_h1 + (size_t)n * D_H1;     // [n*128]

    float* buf;  cudaGetSymbolAddress((void**)&buf, g_buf);
    float* z;    cudaGetSymbolAddress((void**)&z, g_z);

    const int TB = 256;

    // --- CSR build: degree -> (dis + range alloc) -> scatter ---
    zero_deg_kernel<<<(n + TB - 1) / TB, TB>>>(n);
    count_deg_kernel<<<(e + TB - 1) / TB, TB>>>(dst, e);
    alloc_ranges_kernel<<<(n + TB - 1) / TB, TB>>>(n);
    scatter_kernel<<<(e + TB - 1) / TB, TB>>>(src, dst, e);

    const int aggBlocks = (n * 32 + TB - 1) / TB;

    // ===== Layer 1: xhat = A_hat @ x (128-wide), then h1 = relu(xhat@W1+b1)
    csr_agg128_kernel<false, false><<<aggBlocks, TB>>>(x, buf, nullptr, nullptr,
                                                       nullptr, n);
    {
        dim3 grid(D_H1 / 128, (n + 127) / 128);
        sgemm_kernel<128, true><<<grid, TB>>>(buf, W1, b1, out_h1, n, D_IN, D_H1);
    }

    // ===== Layer 2: tmp = h1@W2, then h2 = relu(A_hat@tmp + b2), z = h2@W3
    {
        dim3 grid(D_H2 / 128, (n + 63) / 64);
        sgemm_kernel<64, false><<<grid, TB>>>(out_h1, W2, nullptr, buf, n, D_H1,
                                              D_H2);
    }
    csr_agg128_kernel<true, true><<<aggBlocks, TB>>>(buf, out_h2, b2, W3, z, n);

    // ===== Layer 3: y = A_hat @ z + b3
    csr_agg1_kernel<<<aggBlocks, TB>>>(z, b3, out_y, n);
}

// round 14
// speedup vs baseline: 1.3225x; 1.0044x over previous
#include <cuda_runtime.h>
#include <cuda_bf16.h>
#include <cstdint>

// Problem constants (match reference_code)
#define NN 50000
#define EE 800000
#define D_IN  128
#define D_H1  256
#define D_H2  128

// ---------------------------------------------------------------------------
// Static device scratch (allocation-free rule: __device__ globals)
// ---------------------------------------------------------------------------
__device__ float g_buf[(size_t)NN * 128];    // xhat (L1) / tmp (L2), reused
__device__ float g_z[NN];                    // h2 @ W3 (pre-aggregation)
__device__ float g_dis[NN];                  // rsqrt(deg+1)
__device__ int   g_deg[NN];
__device__ int   g_rowstart[NN];             // CSR range begin (by dst)
__device__ int   g_cursor[NN];               // scatter cursors
__device__ int   g_total;                    // range allocator
__device__ int   g_ssrc[EE];                 // dst-sorted src indices
__device__ float g_snorm[EE];                // dst-sorted edge norms

// ---------------------------------------------------------------------------
// CSR build
// ---------------------------------------------------------------------------
__global__ void zero_deg_kernel(int n) {
    int i = blockIdx.x * blockDim.x + threadIdx.x;
    if (i < n) g_deg[i] = 0;
    if (i == 0) g_total = 0;
}

__global__ void count_deg_kernel(const int* __restrict__ dst, int e) {
    int i = blockIdx.x * blockDim.x + threadIdx.x;
    if (i < e) atomicAdd(&g_deg[dst[i]], 1);
}

// Per-block exclusive scan + atomic range reservation. Range order across
// blocks is arbitrary — only per-node contiguity matters. Also computes dis.
__global__ __launch_bounds__(256)
void alloc_ranges_kernel(int n) {
    __shared__ int warp_sums[8];
    __shared__ int base_sh;
    const int tid = threadIdx.x;
    const int lane = tid & 31;
    const int wid = tid >> 5;
    const int idx = blockIdx.x * 256 + tid;

    int v = (idx < n) ? g_deg[idx] : 0;
    if (idx < n) g_dis[idx] = rsqrtf((float)(v + 1));  // +1 self loop

    // warp inclusive scan
    int incl = v;
#pragma unroll
    for (int o = 1; o < 32; o <<= 1) {
        int t = __shfl_up_sync(0xffffffffu, incl, o);
        if (lane >= o) incl += t;
    }
    if (lane == 31) warp_sums[wid] = incl;
    __syncthreads();

    if (wid == 0) {
        int t = (lane < 8) ? warp_sums[lane] : 0;
        int s = t;
#pragma unroll
        for (int o = 1; o < 8; o <<= 1) {
            int u = __shfl_up_sync(0xffffffffu, s, o);
            if (lane >= o) s += u;
        }
        if (lane < 8) warp_sums[lane] = s - t;  // exclusive warp offsets
        if (lane == 7) base_sh = atomicAdd(&g_total, s);  // block total
    }
    __syncthreads();

    if (idx < n) {
        int excl = base_sh + warp_sums[wid] + (incl - v);
        g_rowstart[idx] = excl;
        g_cursor[idx] = excl;
    }
}

__global__ void scatter_kernel(const int* __restrict__ src,
                               const int* __restrict__ dst, int e) {
    int i = blockIdx.x * blockDim.x + threadIdx.x;
    if (i >= e) return;
    int s = src[i];
    int d = dst[i];
    int pos = atomicAdd(&g_cursor[d], 1);
    g_ssrc[pos] = s;
    g_snorm[pos] = g_dis[s] * g_dis[d];
}

// ---------------------------------------------------------------------------
// CSR aggregation, D=128, one warp per dst node.
// out[row] = dis[row]^2 * in[row] + sum_e norm_e * in[src_e]
// EPI: out = relu(out + bias); DOT: z[row] = out . w3
// ---------------------------------------------------------------------------
template <bool EPI, bool DOT>
__global__ __launch_bounds__(256)
void csr_agg128_kernel(const float* __restrict__ in, float* __restrict__ out,
                       const float* __restrict__ bias,
                       const float* __restrict__ w3,
                       float* __restrict__ z, int n) {
    int gw = (blockIdx.x * blockDim.x + threadIdx.x) >> 5;
    if (gw >= n) return;
    int lane = threadIdx.x & 31;

    int beg = __ldg(&g_rowstart[gw]);
    int end = beg + __ldg(&g_deg[gw]);
    float dis = g_dis[gw];
    float d2 = dis * dis;

    float4 sv = __ldg((const float4*)(in + (size_t)gw * 128) + lane);
    float4 acc = make_float4(d2 * sv.x, d2 * sv.y, d2 * sv.z, d2 * sv.w);

    for (int p = beg; p < end; p += 32) {
        int cnt = min(32, end - p);
        int sidx = 0;
        float w = 0.f;
        if (lane < cnt) {
            sidx = __ldg(&g_ssrc[p + lane]);
            w = __ldg(&g_snorm[p + lane]);
        }
#pragma unroll 4
        for (int j = 0; j < cnt; j++) {
            int s = __shfl_sync(0xffffffffu, sidx, j);
            float ww = __shfl_sync(0xffffffffu, w, j);
            float4 v = __ldg((const float4*)(in + (size_t)s * 128) + lane);
            acc.x = fmaf(ww, v.x, acc.x);
            acc.y = fmaf(ww, v.y, acc.y);
            acc.z = fmaf(ww, v.z, acc.z);
            acc.w = fmaf(ww, v.w, acc.w);
        }
    }

    if (EPI) {
        float4 bb = __ldg((const float4*)bias + lane);
        acc.x = fmaxf(acc.x + bb.x, 0.f);
        acc.y = fmaxf(acc.y + bb.y, 0.f);
        acc.z = fmaxf(acc.z + bb.z, 0.f);
        acc.w = fmaxf(acc.w + bb.w, 0.f);
    }
    ((float4*)(out + (size_t)gw * 128))[lane] = acc;

    if (DOT) {
        float4 wv = __ldg((const float4*)w3 + lane);
        float s = acc.x * wv.x + acc.y * wv.y + acc.z * wv.z + acc.w * wv.w;
#pragma unroll
        for (int o = 16; o; o >>= 1) s += __shfl_xor_sync(0xffffffffu, s, o);
        if (lane == 0) z[gw] = s;
    }
}

// Scalar CSR aggregation for the 1-wide final layer. One warp per dst node.
__global__ __launch_bounds__(256)
void csr_agg1_kernel(const float* __restrict__ zin,
                     const float* __restrict__ b3,
                     float* __restrict__ y, int n) {
    int gw = (blockIdx.x * blockDim.x + threadIdx.x) >> 5;
    if (gw >= n) return;
    int lane = threadIdx.x & 31;
    int beg = __ldg(&g_rowstart[gw]);
    int end = beg + __ldg(&g_deg[gw]);
    float acc = 0.f;
    for (int p = beg + lane; p < end; p += 32)
        acc = fmaf(__ldg(&g_snorm[p]), __ldg(&zin[__ldg(&g_ssrc[p])]), acc);
#pragma unroll
    for (int o = 16; o; o >>= 1) acc += __shfl_xor_sync(0xffffffffu, acc, o);
    if (lane == 0) {
        float dis = g_dis[gw];
        y[gw] = acc + dis * dis * zin[gw] + b3[0];
    }
}

// ---------------------------------------------------------------------------
// SGEMM: C[n x m] = A[n x k] @ B[k x m], fp32, row-major.
// BM x 128 tile, BK=8, 256 threads, (BM/16) x 8 per thread, double-buffered.
// k multiple of 8, m multiple of 128. Optional fused bias + relu.
// ---------------------------------------------------------------------------
template <int BM, bool BIAS_RELU>
__global__ __launch_bounds__(256)
void sgemm_kernel(const float* __restrict__ A, const float* __restrict__ B,
                  const float* __restrict__ bias, float* __restrict__ C,
                  int n, int k, int m) {
    constexpr int BN = 128, BK = 8;
    constexpr int R = BM / 16;            // rows per thread (4 or 8)
    constexpr int AVEC = BM * BK / 4;     // float4s in A tile (128 or 256)
    __shared__ float As[2][BK][BM];
    __shared__ float Bs[2][BK][BN];

    const int tid = threadIdx.x;
    const int rowBase = blockIdx.y * BM;
    const int colBase = blockIdx.x * BN;

    // A loader: BM rows x 8 k = AVEC float4 over first AVEC threads
    const int ar = tid >> 1;              // row in tile
    const int ak = (tid & 1) * 4;         // 0 or 4
    const bool aload = (tid < AVEC);
    // B loader: 8 rows x 128 cols = 256 float4
    const int br = tid >> 5;              // 0..7
    const int bc = (tid & 31) * 4;        // 0..124

    const int tx = tid & 15;              // col group (8 cols each)
    const int ty = tid >> 4;              // row group (R rows each)

    float acc[R][8];
#pragma unroll
    for (int i = 0; i < R; i++)
#pragma unroll
        for (int j = 0; j < 8; j++) acc[i][j] = 0.f;

    const int nk = k / BK;
    const int grow = rowBase + ar;

    // prologue: tile 0
    float4 pA = make_float4(0.f, 0.f, 0.f, 0.f);
    if (aload && grow < n) pA = *(const float4*)(A + (size_t)grow * k + ak);
    float4 pB = *(const float4*)(B + (size_t)br * m + colBase + bc);
    if (aload) {
        As[0][ak + 0][ar] = pA.x;
        As[0][ak + 1][ar] = pA.y;
        As[0][ak + 2][ar] = pA.z;
        As[0][ak + 3][ar] = pA.w;
    }
    *(float4*)&Bs[0][br][bc] = pB;
    __syncthreads();

    for (int kt = 0; kt < nk; kt++) {
        const int cur = kt & 1;
        if (kt + 1 < nk) {
            int k0 = (kt + 1) * BK;
            pA = make_float4(0.f, 0.f, 0.f, 0.f);
            if (aload && grow < n)
                pA = *(const float4*)(A + (size_t)grow * k + k0 + ak);
            pB = *(const float4*)(B + (size_t)(k0 + br) * m + colBase + bc);
        }

#pragma unroll
        for (int kk = 0; kk < BK; kk++) {
            float a[R], b[8];
#pragma unroll
            for (int i = 0; i < R; i += 4)
                *(float4*)&a[i] = *(const float4*)&As[cur][kk][ty * R + i];
            *(float4*)&b[0] = *(const float4*)&Bs[cur][kk][tx * 8];
            *(float4*)&b[4] = *(const float4*)&Bs[cur][kk][tx * 8 + 4];
#pragma unroll
            for (int i = 0; i < R; i++)
#pragma unroll
                for (int j = 0; j < 8; j++)
                    acc[i][j] = fmaf(a[i], b[j], acc[i][j]);
        }

        if (kt + 1 < nk) {
            const int nxt = cur ^ 1;
            if (aload) {
                As[nxt][ak + 0][ar] = pA.x;
                As[nxt][ak + 1][ar] = pA.y;
                As[nxt][ak + 2][ar] = pA.z;
                As[nxt][ak + 3][ar] = pA.w;
            }
            *(float4*)&Bs[nxt][br][bc] = pB;
            __syncthreads();
        }
    }

    // epilogue
    float4 bias0 = make_float4(0.f, 0.f, 0.f, 0.f);
    float4 bias1 = make_float4(0.f, 0.f, 0.f, 0.f);
    if (BIAS_RELU) {
        bias0 = *(const float4*)(bias + colBase + tx * 8);
        bias1 = *(const float4*)(bias + colBase + tx * 8 + 4);
    }
#pragma unroll
    for (int i = 0; i < R; i++) {
        int r = rowBase + ty * R + i;
        if (r >= n) break;
        float4 o0 = make_float4(acc[i][0], acc[i][1], acc[i][2], acc[i][3]);
        float4 o1 = make_float4(acc[i][4], acc[i][5], acc[i][6], acc[i][7]);
        if (BIAS_RELU) {
            o0.x = fmaxf(o0.x + bias0.x, 0.f);
            o0.y = fmaxf(o0.y + bias0.y, 0.f);
            o0.z = fmaxf(o0.z + bias0.z, 0.f);
            o0.w = fmaxf(o0.w + bias0.w, 0.f);
            o1.x = fmaxf(o1.x + bias1.x, 0.f);
            o1.y = fmaxf(o1.y + bias1.y, 0.f);
            o1.z = fmaxf(o1.z + bias1.z, 0.f);
            o1.w = fmaxf(o1.w + bias1.w, 0.f);
        }
        *(float4*)(C + (size_t)r * m + colBase + tx * 8) = o0;
        *(float4*)(C + (size_t)r * m + colBase + tx * 8 + 4) = o1;
    }
}

// ---------------------------------------------------------------------------
// Launch
// ---------------------------------------------------------------------------
extern "C" void kernel_launch(void* const* d_in, const int* in_sizes, int n_in,
                              void* d_out, int out_size) {
    const float* x  = (const float*)d_in[0];
    const int*   ei = (const int*)d_in[1];
    const float* W1 = (const float*)d_in[2];
    const float* b1 = (const float*)d_in[3];
    const float* W2 = (const float*)d_in[4];
    const float* b2 = (const float*)d_in[5];
    const float* W3 = (const float*)d_in[6];
    const float* b3 = (const float*)d_in[7];

    const int n = NN;
    const int e = EE;
    const int* src = ei;
    const int* dst = ei + e;

    float* out_y  = (float*)d_out;                 // [n]
    float* out_h1 = out_y + n;                     // [n*256]
    float* out_h2 = out_h1 + (size_t)n * D_H1;     // [n*128]

    float* buf;  cudaGetSymbolAddress((void**)&buf, g_buf);
    float* z;    cudaGetSymbolAddress((void**)&z, g_z);

    const int TB = 256;

    // --- CSR build: degree -> (dis + range alloc) -> scatter ---
    zero_deg_kernel<<<(n + TB - 1) / TB, TB>>>(n);
    count_deg_kernel<<<(e + TB - 1) / TB, TB>>>(dst, e);
    alloc_ranges_kernel<<<(n + TB - 1) / TB, TB>>>(n);
    scatter_kernel<<<(e + TB - 1) / TB, TB>>>(src, dst, e);

    const int aggBlocks = (n * 32 + TB - 1) / TB;

    // ===== Layer 1: xhat = A_hat @ x (128-wide), then h1 = relu(xhat@W1+b1)
    csr_agg128_kernel<false, false><<<aggBlocks, TB>>>(x, buf, nullptr, nullptr,
                                                       nullptr, n);
    {
        dim3 grid(D_H1 / 128, (n + 127) / 128);
        sgemm_kernel<128, true><<<grid, TB>>>(buf, W1, b1, out_h1, n, D_IN, D_H1);
    }

    // ===== Layer 2: tmp = h1@W2, then h2 = relu(A_hat@tmp + b2), z = h2@W3
    {
        dim3 grid(D_H2 / 128, (n + 63) / 64);
        sgemm_kernel<64, false><<<grid, TB>>>(out_h1, W2, nullptr, buf, n, D_H1,
                                              D_H2);
    }
    csr_agg128_kernel<true, true><<<aggBlocks, TB>>>(buf, out_h2, b2, W3, z, n);

    // ===== Layer 3: y = A_hat @ z + b3
    csr_agg1_kernel<<<aggBlocks, TB>>>(z, b3, out_y, n);
}